// round 2
// baseline (speedup 1.0000x reference)
#include <cuda_runtime.h>
#include <cstdint>

#define CIN   64
#define COUT  64
#define Hh    224
#define Ww    224
#define NB    16
#define TH    16
#define TW    16
#define CI_CHUNK 8
#define XS_W  20   // 18 cols padded to 20 (float2 elements)

// Ternarized weights, layout [e][co] with e = ci*9 + ky*3 + kx (co contiguous).
__device__ float g_wq[CIN * 9 * COUT];

// ---------------------------------------------------------------------------
// Kernel 1: ternarize weights (one block per output channel)
// ---------------------------------------------------------------------------
__global__ void ternarize_kernel(const float* __restrict__ w) {
    __shared__ float red[256];
    __shared__ float red2[256];
    const int co  = blockIdx.x;
    const int tid = threadIdx.x;
    const float* wf = w + co * 576;

    float s = 0.f;
    for (int i = tid; i < 576; i += 256) s += fabsf(wf[i]);
    red[tid] = s;
    __syncthreads();
    for (int o = 128; o > 0; o >>= 1) {
        if (tid < o) red[tid] += red[tid + o];
        __syncthreads();
    }
    const float delta = (0.7f / 576.f) * red[0];
    __syncthreads();

    float cnt = 0.f, ms = 0.f;
    for (int i = tid; i < 576; i += 256) {
        float a = fabsf(wf[i]);
        if (a > delta) { cnt += 1.f; ms += a; }
    }
    red[tid] = ms; red2[tid] = cnt;
    __syncthreads();
    for (int o = 128; o > 0; o >>= 1) {
        if (tid < o) { red[tid] += red[tid + o]; red2[tid] += red2[tid + o]; }
        __syncthreads();
    }
    float count = (red2[0] == 0.f) ? 1.f : red2[0];
    float alpha = fmaxf(red[0] / count, 1e-4f);

    for (int i = tid; i < 576; i += 256) {
        float v = wf[i];
        float t = (v > delta) ? alpha : ((v < -delta) ? -alpha : 0.f);
        g_wq[i * COUT + co] = t;
    }
}

// ---------------------------------------------------------------------------
// Packed f32x2 FMA helpers
// ---------------------------------------------------------------------------
__device__ __forceinline__ void fma2(unsigned long long& d,
                                     unsigned long long a,
                                     unsigned long long b) {
    asm("fma.rn.f32x2 %0, %1, %2, %0;" : "+l"(d) : "l"(a), "l"(b));
}
__device__ __forceinline__ unsigned long long pack2(float lo, float hi) {
    unsigned long long r;
    asm("mov.b64 %0, {%1, %2};" : "=l"(r) : "f"(lo), "f"(hi));
    return r;
}
__device__ __forceinline__ void unpack2(unsigned long long v, float& lo, float& hi) {
    asm("mov.b64 {%0, %1}, %2;" : "=f"(lo), "=f"(hi) : "l"(v));
}

// ---------------------------------------------------------------------------
// Kernel 2: direct conv, 16x16 pixel tile x 64 couts per block.
// 256 threads = 8 co-groups (8 couts each) x 32 pixel-threads
// (pixel-thread: row = pix/2 in 0..15, wseg = pix%2, 8 consecutive w).
// x staged in smem duplicated {v,v} so FFMA2's broadcast operand is one LDS.64.
// ---------------------------------------------------------------------------
__global__ __launch_bounds__(256, 2)
void conv_kernel(const float* __restrict__ x,
                 const float* __restrict__ bias,
                 float* __restrict__ out) {
    __shared__ float2 xs2[CI_CHUNK][18][XS_W];
    __shared__ float  ws[CI_CHUNK][9][COUT];

    const int tid    = threadIdx.x;
    const int co_grp = tid >> 5;      // 0..7
    const int pix    = tid & 31;      // 0..31
    const int row    = pix >> 1;      // 0..15
    const int wseg   = pix & 1;       // 0..1
    const int co0    = co_grp * 8;

    const int n  = blockIdx.z;
    const int h0 = blockIdx.y * TH;
    const int w0 = blockIdx.x * TW;

    // Accumulators: 4 co-pairs x 8 pixels (packed f32x2 over the co pair)
    unsigned long long acc2[4][8];
    #pragma unroll
    for (int d = 0; d < 4; d++) {
        unsigned long long b = pack2(__ldg(&bias[co0 + 2 * d]),
                                     __ldg(&bias[co0 + 2 * d + 1]));
        #pragma unroll
        for (int p = 0; p < 8; p++) acc2[d][p] = b;
    }

    const float* xn = x + (size_t)n * CIN * Hh * Ww;

    for (int ci0 = 0; ci0 < CIN; ci0 += CI_CHUNK) {
        // Stage input halo tile: 8 ci x 18 x 18, duplicated {v,v}
        for (int idx = tid; idx < CI_CHUNK * 18 * 18; idx += 256) {
            int cl  = idx / 324;
            int rem = idx - cl * 324;
            int r   = rem / 18;
            int c   = rem - r * 18;
            int gh  = h0 + r - 1;
            int gw  = w0 + c - 1;
            float v = 0.f;
            if ((unsigned)gh < (unsigned)Hh && (unsigned)gw < (unsigned)Ww)
                v = xn[((size_t)(ci0 + cl) * Hh + gh) * Ww + gw];
            xs2[cl][r][c] = make_float2(v, v);
        }
        // Stage weight chunk: straight copy, layout already [e][co]
        const float* wsrc = g_wq + (size_t)ci0 * 9 * COUT;
        float* wdst = &ws[0][0][0];
        for (int idx = tid; idx < CI_CHUNK * 9 * COUT; idx += 256)
            wdst[idx] = wsrc[idx];
        __syncthreads();

        #pragma unroll 2
        for (int cl = 0; cl < CI_CHUNK; cl++) {
            #pragma unroll
            for (int dh = 0; dh < 3; dh++) {
                unsigned long long xp[10];
                const unsigned long long* xrow =
                    (const unsigned long long*)&xs2[cl][row + dh][wseg * 8];
                #pragma unroll
                for (int j = 0; j < 10; j++) xp[j] = xrow[j];

                #pragma unroll
                for (int dw = 0; dw < 3; dw++) {
                    const int tap = dh * 3 + dw;
                    ulonglong2 w01 = *(const ulonglong2*)&ws[cl][tap][co0];
                    ulonglong2 w23 = *(const ulonglong2*)&ws[cl][tap][co0 + 4];
                    #pragma unroll
                    for (int p = 0; p < 8; p++) {
                        fma2(acc2[0][p], w01.x, xp[p + dw]);
                        fma2(acc2[1][p], w01.y, xp[p + dw]);
                        fma2(acc2[2][p], w23.x, xp[p + dw]);
                        fma2(acc2[3][p], w23.y, xp[p + dw]);
                    }
                }
            }
        }
        __syncthreads();
    }

    // Write 8 couts x 8 pixels, vectorized float4
    const int h  = h0 + row;
    const int wb = w0 + wseg * 8;
    #pragma unroll
    for (int d = 0; d < 4; d++) {
        float lo[8], hi[8];
        #pragma unroll
        for (int p = 0; p < 8; p++) unpack2(acc2[d][p], lo[p], hi[p]);
        float* o0 = out + (((size_t)n * COUT + co0 + 2 * d) * Hh + h) * Ww + wb;
        float* o1 = o0 + (size_t)Hh * Ww;
        ((float4*)o0)[0] = make_float4(lo[0], lo[1], lo[2], lo[3]);
        ((float4*)o0)[1] = make_float4(lo[4], lo[5], lo[6], lo[7]);
        ((float4*)o1)[0] = make_float4(hi[0], hi[1], hi[2], hi[3]);
        ((float4*)o1)[1] = make_float4(hi[4], hi[5], hi[6], hi[7]);
    }
}

// ---------------------------------------------------------------------------
extern "C" void kernel_launch(void* const* d_in, const int* in_sizes, int n_in,
                              void* d_out, int out_size) {
    const float* x      = (const float*)d_in[0];
    const float* weight = (const float*)d_in[1];
    const float* bias   = (const float*)d_in[2];
    float* out          = (float*)d_out;

    ternarize_kernel<<<COUT, 256>>>(weight);
    dim3 grid(Ww / TW, Hh / TH, NB);
    conv_kernel<<<grid, 256>>>(x, bias, out);
}

// round 6
// speedup vs baseline: 2.2689x; 2.2689x over previous
#include <cuda_runtime.h>
#include <cuda_bf16.h>
#include <cstdint>

#define CIN   64
#define COUT  64
#define HH    224
#define WW    224

// ---------------- smem layout (bytes) ----------------
// W: [tap][co][ci] bf16, per-co 128B rows, XOR-swizzled  -> 9*64*128 = 73728
// A: 514 position-rows x 256B (units 0-7 = hi octets, 8-15 = lo octets)
#define WS_OFF    0
#define WS_BYTES  (9 * 64 * 128)
#define A_OFF     (WS_OFF + WS_BYTES)          // 73728 (1024-aligned)
#define A_ROWS    514
#define A_BYTES   (A_ROWS * 256)               // 131584
#define ALPHA_OFF (A_OFF + A_BYTES)            // 205312
#define BIAS_OFF  (ALPHA_OFF + 256)
#define SMEM_TOTAL (BIAS_OFF + 256)            // 205824

// Ternary pattern (exact in bf16), layout [tap][co][ci]
__device__ __nv_bfloat16 g_wt[9 * COUT * CIN];
__device__ float g_alpha[COUT];

// ---------------------------------------------------------------------------
// Kernel 1: ternarize -> bf16 {-1,0,+1} pattern + per-cout alpha
// ---------------------------------------------------------------------------
__global__ void ternarize_kernel(const float* __restrict__ w) {
    __shared__ float red[256];
    __shared__ float red2[256];
    const int co  = blockIdx.x;
    const int tid = threadIdx.x;
    const float* wf = w + co * 576;

    float s = 0.f;
    for (int i = tid; i < 576; i += 256) s += fabsf(wf[i]);
    red[tid] = s;
    __syncthreads();
    for (int o = 128; o > 0; o >>= 1) {
        if (tid < o) red[tid] += red[tid + o];
        __syncthreads();
    }
    const float delta = (0.7f / 576.f) * red[0];
    __syncthreads();

    float cnt = 0.f, ms = 0.f;
    for (int i = tid; i < 576; i += 256) {
        float a = fabsf(wf[i]);
        if (a > delta) { cnt += 1.f; ms += a; }
    }
    red[tid] = ms; red2[tid] = cnt;
    __syncthreads();
    for (int o = 128; o > 0; o >>= 1) {
        if (tid < o) { red[tid] += red[tid + o]; red2[tid] += red2[tid + o]; }
        __syncthreads();
    }
    float count = (red2[0] == 0.f) ? 1.f : red2[0];
    float alpha = fmaxf(red[0] / count, 1e-4f);
    if (tid == 0) g_alpha[co] = alpha;

    // w index: [co][ci][tap]; emit g_wt[tap][co][ci]
    for (int i = tid; i < 576; i += 256) {
        int ci  = i / 9;
        int tap = i - ci * 9;
        float v = wf[i];
        float t = (v > delta) ? 1.f : ((v < -delta) ? -1.f : 0.f);
        g_wt[(tap * COUT + co) * CIN + ci] = __float2bfloat16(t);
    }
}

// ---------------------------------------------------------------------------
// Baseline-PTX tensor helpers (supported on plain sm_103 target)
// ---------------------------------------------------------------------------
__device__ __forceinline__ uint32_t smem_u32(const void* p) {
    uint32_t a;
    asm("{ .reg .u64 t; cvta.to.shared.u64 t, %1; cvt.u32.u64 %0, t; }" : "=r"(a) : "l"(p));
    return a;
}

__device__ __forceinline__ void ldsm_x4(uint32_t* r, uint32_t addr) {
    asm volatile("ldmatrix.sync.aligned.m8n8.x4.shared.b16 {%0,%1,%2,%3}, [%4];"
                 : "=r"(r[0]), "=r"(r[1]), "=r"(r[2]), "=r"(r[3]) : "r"(addr));
}
__device__ __forceinline__ void ldsm_x2(uint32_t* r, uint32_t addr) {
    asm volatile("ldmatrix.sync.aligned.m8n8.x2.shared.b16 {%0,%1}, [%2];"
                 : "=r"(r[0]), "=r"(r[1]) : "r"(addr));
}
__device__ __forceinline__ void mma16816(float* d, const uint32_t* a, const uint32_t* b) {
    asm volatile("mma.sync.aligned.m16n8k16.row.col.f32.bf16.bf16.f32 "
                 "{%0,%1,%2,%3}, {%4,%5,%6,%7}, {%8,%9}, {%0,%1,%2,%3};"
                 : "+f"(d[0]), "+f"(d[1]), "+f"(d[2]), "+f"(d[3])
                 : "r"(a[0]), "r"(a[1]), "r"(a[2]), "r"(a[3]), "r"(b[0]), "r"(b[1]));
}

// ---------------------------------------------------------------------------
// Kernel 2: bf16 mma.sync implicit conv.
// CTA strip: 8 input rows x 64 cols (6x62 valid outputs), positions 0..511,
// A row p+1 holds position p: 128 bf16 k-entries (64 hi ci, 64 lo ci).
// 3 M=128 tiles x N=64 couts; warp tile m32 x n32 (8 warps = 4M x 2N).
// K per tap = 2 halves x 4 k16-chunks; B frags loaded once per tap.
// ---------------------------------------------------------------------------
__global__ __launch_bounds__(256, 1)
void conv_mma_kernel(const float* __restrict__ x,
                     const float* __restrict__ bias,
                     float* __restrict__ out) {
    extern __shared__ char smem[];
    const uint32_t sb  = smem_u32(smem);
    const int tid  = threadIdx.x;
    const int wid  = tid >> 5;
    const int lane = tid & 31;

    const int w0 = blockIdx.x * 62;
    const int h0 = blockIdx.y * 6;
    const int n  = blockIdx.z;

    // ---- stage W: g_wt[tap][co][ci] -> smem, unit u = ci>>3 swizzled by co&7
    {
        const uint32_t* src = (const uint32_t*)g_wt;        // 2 ci per word
        for (int i = tid; i < 9 * 64 * 64 / 2; i += 256) {
            int e   = i * 2;
            int tap = e >> 12;
            int co  = (e >> 6) & 63;
            int ci  = e & 63;
            uint32_t b = (uint32_t)(tap * 8192 + co * 128)
                       + ((((ci >> 3) ^ (co & 7)) << 4) | ((ci & 7) * 2));
            *(uint32_t*)(smem + WS_OFF + b) = src[i];
        }
    }
    if (tid < 64) {
        *(float*)(smem + ALPHA_OFF + tid * 4) = g_alpha[tid];
        *(float*)(smem + BIAS_OFF  + tid * 4) = __ldg(&bias[tid]);
    }
    // zero guard rows 0 and 513
    if (tid < 128) {
        int off = (tid < 64) ? tid * 4 : (513 * 256 + (tid - 64) * 4);
        *(float*)(smem + A_OFF + off) = 0.f;
    }

    // ---- stage A: strip -> hi/lo bf16, one 16B unit (8 ci) per task
    {
        const float* xn = x + (size_t)n * CIN * HH * WW;
        for (int i = tid; i < 4096; i += 256) {       // 512 pos x 8 octets
            int p = i & 511;
            int o = i >> 9;
            int r = p >> 6, c = p & 63;
            int h = h0 + r - 1, w = w0 + c - 1;
            bool inb = ((unsigned)h < HH) && ((unsigned)w < WW);
            uint32_t hiw[4], low[4];
            #pragma unroll
            for (int j = 0; j < 4; j++) {
                float v0 = 0.f, v1 = 0.f;
                if (inb) {
                    const float* bp = xn + ((size_t)(o * 8 + 2 * j) * HH + h) * WW + w;
                    v0 = __ldg(bp);
                    v1 = __ldg(bp + (size_t)HH * WW);
                }
                __nv_bfloat16 h0b = __float2bfloat16(v0);
                __nv_bfloat16 h1b = __float2bfloat16(v1);
                __nv_bfloat16 l0b = __float2bfloat16(v0 - __bfloat162float(h0b));
                __nv_bfloat16 l1b = __float2bfloat16(v1 - __bfloat162float(h1b));
                hiw[j] = (uint32_t)__bfloat16_as_ushort(h0b)
                       | ((uint32_t)__bfloat16_as_ushort(h1b) << 16);
                low[j] = (uint32_t)__bfloat16_as_ushort(l0b)
                       | ((uint32_t)__bfloat16_as_ushort(l1b) << 16);
            }
            int row = p + 1;
            uint32_t base = (uint32_t)(A_OFF + row * 256);
            uint32_t sw   = (uint32_t)((o ^ (row & 7)) << 4);
            *(uint4*)(smem + base + sw)         = make_uint4(hiw[0], hiw[1], hiw[2], hiw[3]);
            *(uint4*)(smem + base + (sw | 128)) = make_uint4(low[0], low[1], low[2], low[3]);
        }
    }
    __syncthreads();

    // ---- compute
    const int wm = wid & 3;          // 0..3 (M)
    const int wn = wid >> 2;         // 0..1 (N)
    const int n0 = wn * 32;

    const int bl_row = lane & 7;             // B: co row within n-chunk
    const int bl_u   = (lane >> 3) & 1;      // B: k half of k16
    const int al_row = lane & 15;            // A: row within m16
    const int al_u   = lane >> 4;            // A: k half of k16

    const float* al = (const float*)(smem + ALPHA_OFF);
    const float* bi = (const float*)(smem + BIAS_OFF);

    for (int t = 0; t < 3; t++) {
        float acc[2][4][4];
        #pragma unroll
        for (int mc = 0; mc < 2; mc++)
            #pragma unroll
            for (int nc = 0; nc < 4; nc++)
                #pragma unroll
                for (int q = 0; q < 4; q++) acc[mc][nc][q] = 0.f;

        const int p0 = 64 + t * 128 + wm * 32;

        #pragma unroll
        for (int tap = 0; tap < 9; tap++) {
            const int shift = (tap / 3) * 64 + (tap % 3) - 65;

            // B fragments for this tap: reused for hi and lo halves
            uint32_t bfr[4][4][2];
            #pragma unroll
            for (int kc = 0; kc < 4; kc++)
                #pragma unroll
                for (int nc = 0; nc < 4; nc++) {
                    int row = n0 + nc * 8 + bl_row;
                    int u   = kc * 2 + bl_u;
                    uint32_t addr = sb + WS_OFF + (uint32_t)(tap * 8192 + row * 128)
                                  + (uint32_t)((u ^ bl_row) << 4);
                    ldsm_x2(bfr[kc][nc], addr);
                }

            #pragma unroll
            for (int half = 0; half < 2; half++) {
                const int ubase = half * 8;
                #pragma unroll
                for (int kc = 0; kc < 4; kc++) {
                    uint32_t afr[2][4];
                    #pragma unroll
                    for (int mc = 0; mc < 2; mc++) {
                        int row = p0 + 1 + shift + mc * 16 + al_row;
                        int u   = ubase + kc * 2 + al_u;
                        uint32_t addr = sb + A_OFF + (uint32_t)(row * 256)
                                      + (uint32_t)((((u & 8) | ((u & 7) ^ (row & 7))) << 4));
                        ldsm_x4(afr[mc], addr);
                    }
                    #pragma unroll
                    for (int mc = 0; mc < 2; mc++)
                        #pragma unroll
                        for (int nc = 0; nc < 4; nc++)
                            mma16816(acc[mc][nc], afr[mc], bfr[kc][nc]);
                }
            }
        }

        // ---- epilogue: alpha*d + bias, scalar stores (32B row segments/co)
        #pragma unroll
        for (int mc = 0; mc < 2; mc++) {
            const int pb = p0 + mc * 16 + (lane >> 2);
            #pragma unroll
            for (int rr = 0; rr < 2; rr++) {
                const int p = pb + rr * 8;
                const int c = p & 63, r = p >> 6;
                const int h = h0 + r - 1, w = w0 + c - 1;
                if (c >= 1 && c <= 62 && h < HH && w < WW) {
                    float* ob = out + (((size_t)n * COUT) * HH + h) * WW + w;
                    #pragma unroll
                    for (int nc = 0; nc < 4; nc++) {
                        const int co = n0 + nc * 8 + 2 * (lane & 3);
                        float v0 = acc[mc][nc][rr * 2 + 0] * al[co]     + bi[co];
                        float v1 = acc[mc][nc][rr * 2 + 1] * al[co + 1] + bi[co + 1];
                        ob[(size_t)co       * HH * WW] = v0;
                        ob[(size_t)(co + 1) * HH * WW] = v1;
                    }
                }
            }
        }
    }
}

// ---------------------------------------------------------------------------
extern "C" void kernel_launch(void* const* d_in, const int* in_sizes, int n_in,
                              void* d_out, int out_size) {
    const float* x      = (const float*)d_in[0];
    const float* weight = (const float*)d_in[1];
    const float* bias   = (const float*)d_in[2];
    float* out          = (float*)d_out;

    cudaFuncSetAttribute(conv_mma_kernel,
                         cudaFuncAttributeMaxDynamicSharedMemorySize, SMEM_TOTAL);

    ternarize_kernel<<<COUT, 256>>>(weight);
    dim3 grid(4, 38, 16);   // 4 W-strips (62 wide), 38 H-strips (6 tall), N=16
    conv_mma_kernel<<<grid, 256, SMEM_TOTAL>>>(x, bias, out);
}

// round 7
// speedup vs baseline: 4.2416x; 1.8694x over previous
#include <cuda_runtime.h>
#include <cuda_fp16.h>
#include <cstdint>

#define CIN   64
#define COUT  64
#define HH    224
#define WW    224

// ---------------- smem layout (bytes) ----------------
// W: [tap][co][ci] fp16, per-co 128B rows, XOR-swizzle baked in global layout
// A: 514 position-rows x 128B (64 ci fp16), XOR swizzled
#define WS_OFF    0
#define WS_BYTES  (9 * 64 * 128)               // 73728
#define A_OFF     (WS_OFF + WS_BYTES)          // 73728 (1024-aligned)
#define A_ROWS    514
#define A_BYTES   (A_ROWS * 128)               // 65792
#define ALPHA_OFF (A_OFF + A_BYTES)            // 139520
#define BIAS_OFF  (ALPHA_OFF + 256)
#define SMEM_TOTAL (BIAS_OFF + 256)            // 140032

// Ternary pattern (exact in fp16), layout [tap][co][ci] with ldmatrix swizzle baked:
// elem = tap*4096 + co*64 + (((ci>>3)^(co&7))<<3) + (ci&7)
__device__ __half g_wt[9 * COUT * CIN];
__device__ float g_alpha[COUT];

// ---------------------------------------------------------------------------
// Kernel 1: ternarize -> fp16 {-1,0,+1} pattern (pre-swizzled) + per-cout alpha
// ---------------------------------------------------------------------------
__global__ void ternarize_kernel(const float* __restrict__ w) {
    __shared__ float red[256];
    __shared__ float red2[256];
    const int co  = blockIdx.x;
    const int tid = threadIdx.x;
    const float* wf = w + co * 576;

    float s = 0.f;
    for (int i = tid; i < 576; i += 256) s += fabsf(wf[i]);
    red[tid] = s;
    __syncthreads();
    for (int o = 128; o > 0; o >>= 1) {
        if (tid < o) red[tid] += red[tid + o];
        __syncthreads();
    }
    const float delta = (0.7f / 576.f) * red[0];
    __syncthreads();

    float cnt = 0.f, ms = 0.f;
    for (int i = tid; i < 576; i += 256) {
        float a = fabsf(wf[i]);
        if (a > delta) { cnt += 1.f; ms += a; }
    }
    red[tid] = ms; red2[tid] = cnt;
    __syncthreads();
    for (int o = 128; o > 0; o >>= 1) {
        if (tid < o) { red[tid] += red[tid + o]; red2[tid] += red2[tid + o]; }
        __syncthreads();
    }
    float count = (red2[0] == 0.f) ? 1.f : red2[0];
    float alpha = fmaxf(red[0] / count, 1e-4f);
    if (tid == 0) g_alpha[co] = alpha;

    // w index: [co][ci][tap]; emit pre-swizzled g_wt[tap][co][ci]
    for (int i = tid; i < 576; i += 256) {
        int ci  = i / 9;
        int tap = i - ci * 9;
        float v = wf[i];
        float t = (v > delta) ? 1.f : ((v < -delta) ? -1.f : 0.f);
        int usw = (ci >> 3) ^ (co & 7);
        g_wt[tap * 4096 + co * 64 + usw * 8 + (ci & 7)] = __float2half_rn(t);
    }
}

// ---------------------------------------------------------------------------
// Baseline-PTX helpers
// ---------------------------------------------------------------------------
__device__ __forceinline__ uint32_t smem_u32(const void* p) {
    uint32_t a;
    asm("{ .reg .u64 t; cvta.to.shared.u64 t, %1; cvt.u32.u64 %0, t; }" : "=r"(a) : "l"(p));
    return a;
}
__device__ __forceinline__ void ldsm_x4(uint32_t* r, uint32_t addr) {
    asm volatile("ldmatrix.sync.aligned.m8n8.x4.shared.b16 {%0,%1,%2,%3}, [%4];"
                 : "=r"(r[0]), "=r"(r[1]), "=r"(r[2]), "=r"(r[3]) : "r"(addr));
}
__device__ __forceinline__ void mma16816(float* d, const uint32_t* a, const uint32_t* b) {
    asm volatile("mma.sync.aligned.m16n8k16.row.col.f32.f16.f16.f32 "
                 "{%0,%1,%2,%3}, {%4,%5,%6,%7}, {%8,%9}, {%0,%1,%2,%3};"
                 : "+f"(d[0]), "+f"(d[1]), "+f"(d[2]), "+f"(d[3])
                 : "r"(a[0]), "r"(a[1]), "r"(a[2]), "r"(a[3]), "r"(b[0]), "r"(b[1]));
}
__device__ __forceinline__ void cpasync16(uint32_t dst, const void* src) {
    asm volatile("cp.async.cg.shared.global [%0], [%1], 16;" :: "r"(dst), "l"(src) : "memory");
}

// ---------------------------------------------------------------------------
// Kernel 2: fp16 mma.sync implicit conv.
// CTA strip: 8 input rows x 64 cols (6x62 valid outputs), positions 0..511,
// A row p+1: 64 fp16 ci (128B). 3 M=128 tiles x N=64 couts.
// 16 warps: warp tile m16 (wid&7) x n32 (wid>>3).
// tap-outer / tile-inner: B frags per tap reused across all 3 tiles.
// ---------------------------------------------------------------------------
__global__ __launch_bounds__(512, 1)
void conv_mma_kernel(const float* __restrict__ x,
                     const float* __restrict__ bias,
                     float* __restrict__ out) {
    extern __shared__ char smem[];
    const uint32_t sb  = smem_u32(smem);
    const int tid  = threadIdx.x;
    const int wid  = tid >> 5;
    const int lane = tid & 31;

    const int w0 = blockIdx.x * 62;
    const int h0 = blockIdx.y * 6;
    const int n  = blockIdx.z;

    // ---- stage W via cp.async: global layout already swizzled, linear 16B copy
    {
        const char* src = (const char*)g_wt;
        for (int i = tid; i < 9 * 64 * 8; i += 512)
            cpasync16(sb + WS_OFF + i * 16, src + i * 16);
        asm volatile("cp.async.commit_group;" ::: "memory");
    }
    if (tid < 64) {
        *(float*)(smem + ALPHA_OFF + tid * 4) = g_alpha[tid];
        *(float*)(smem + BIAS_OFF  + tid * 4) = __ldg(&bias[tid]);
    }
    // zero guard rows 0 and 513 (128B each)
    if (tid < 64) {
        int off = (tid < 32) ? tid * 4 : (513 * 128 + (tid - 32) * 4);
        *(float*)(smem + A_OFF + off) = 0.f;
    }

    // ---- stage A: strip -> fp16, one 16B unit (8 ci) per task
    {
        const float* xn = x + (size_t)n * CIN * HH * WW;
        for (int i = tid; i < 4096; i += 512) {       // 512 pos x 8 octets
            int p = i & 511;
            int o = i >> 9;
            int r = p >> 6, c = p & 63;
            int h = h0 + r - 1, w = w0 + c - 1;
            bool inb = ((unsigned)h < HH) && ((unsigned)w < WW);
            uint32_t hw[4];
            #pragma unroll
            for (int j = 0; j < 4; j++) {
                float v0 = 0.f, v1 = 0.f;
                if (inb) {
                    const float* bp = xn + ((size_t)(o * 8 + 2 * j) * HH + h) * WW + w;
                    v0 = __ldg(bp);
                    v1 = __ldg(bp + (size_t)HH * WW);
                }
                __half2 hv = __floats2half2_rn(v0, v1);
                hw[j] = *(const uint32_t*)&hv;
            }
            int row = p + 1;
            uint32_t off = (uint32_t)(A_OFF + row * 128) + (uint32_t)((o ^ (row & 7)) << 4);
            *(uint4*)(smem + off) = make_uint4(hw[0], hw[1], hw[2], hw[3]);
        }
    }
    asm volatile("cp.async.wait_group 0;" ::: "memory");
    __syncthreads();

    // ---- compute
    const int wm = wid & 7;          // 0..7 (M slice, m16)
    const int wn = wid >> 3;         // 0..1 (N slice, n32)
    const int n0 = wn * 32;

    float acc[3][4][4];
    #pragma unroll
    for (int t = 0; t < 3; t++)
        #pragma unroll
        for (int nc = 0; nc < 4; nc++)
            #pragma unroll
            for (int q = 0; q < 4; q++) acc[t][nc][q] = 0.f;

    const int b_row = lane & 7;
    const int b_uo  = lane >> 3;         // 0..3
    const int a_row = lane & 15;
    const int a_uo  = lane >> 4;         // 0..1

    #pragma unroll 1
    for (int tap = 0; tap < 9; tap++) {
        const int shift = (tap / 3) * 64 + (tap % 3) - 65;

        // B fragments: 2 ldsm_x4 per nc cover kc pairs {0,1} and {2,3}
        uint32_t bfr[4][4][2];
        {
            const uint32_t wbase = sb + WS_OFF + (uint32_t)(tap * 8192);
            #pragma unroll
            for (int nc = 0; nc < 4; nc++) {
                int row = n0 + nc * 8 + b_row;
                #pragma unroll
                for (int kp = 0; kp < 2; kp++) {
                    int u = kp * 4 + b_uo;
                    uint32_t addr = wbase + (uint32_t)(row * 128)
                                  + (uint32_t)((u ^ (row & 7)) << 4);
                    uint32_t r[4];
                    ldsm_x4(r, addr);
                    bfr[kp * 2][nc][0]     = r[0];
                    bfr[kp * 2][nc][1]     = r[1];
                    bfr[kp * 2 + 1][nc][0] = r[2];
                    bfr[kp * 2 + 1][nc][1] = r[3];
                }
            }
        }

        #pragma unroll
        for (int t = 0; t < 3; t++) {
            const int pt = 64 + t * 128 + wm * 16;
            #pragma unroll
            for (int kc = 0; kc < 4; kc++) {
                int row = pt + 1 + shift + a_row;
                int u   = kc * 2 + a_uo;
                uint32_t addr = sb + A_OFF + (uint32_t)(row * 128)
                              + (uint32_t)((u ^ (row & 7)) << 4);
                uint32_t afr[4];
                ldsm_x4(afr, addr);
                #pragma unroll
                for (int nc = 0; nc < 4; nc++)
                    mma16816(acc[t][nc], afr, bfr[kc][nc]);
            }
        }
    }

    // ---- epilogue: alpha*d + bias
    const float* al = (const float*)(smem + ALPHA_OFF);
    const float* bi = (const float*)(smem + BIAS_OFF);
    #pragma unroll
    for (int t = 0; t < 3; t++) {
        const int pt = 64 + t * 128 + wm * 16;
        #pragma unroll
        for (int rr = 0; rr < 2; rr++) {
            const int p = pt + rr * 8 + (lane >> 2);
            const int c = p & 63, r = p >> 6;
            const int h = h0 + r - 1, w = w0 + c - 1;
            if (c >= 1 && c <= 62 && h < HH && w < WW) {
                float* ob = out + (((size_t)n * COUT) * HH + h) * WW + w;
                #pragma unroll
                for (int nc = 0; nc < 4; nc++) {
                    const int co = n0 + nc * 8 + 2 * (lane & 3);
                    float v0 = acc[t][nc][rr * 2 + 0] * al[co]     + bi[co];
                    float v1 = acc[t][nc][rr * 2 + 1] * al[co + 1] + bi[co + 1];
                    ob[(size_t)co       * HH * WW] = v0;
                    ob[(size_t)(co + 1) * HH * WW] = v1;
                }
            }
        }
    }
}

// ---------------------------------------------------------------------------
extern "C" void kernel_launch(void* const* d_in, const int* in_sizes, int n_in,
                              void* d_out, int out_size) {
    const float* x      = (const float*)d_in[0];
    const float* weight = (const float*)d_in[1];
    const float* bias   = (const float*)d_in[2];
    float* out          = (float*)d_out;

    cudaFuncSetAttribute(conv_mma_kernel,
                         cudaFuncAttributeMaxDynamicSharedMemorySize, SMEM_TOTAL);

    ternarize_kernel<<<COUT, 256>>>(weight);
    dim3 grid(4, 38, 16);   // 4 W-strips (62 wide), 38 H-strips (6 tall), N=16
    conv_mma_kernel<<<grid, 512, SMEM_TOTAL>>>(x, bias, out);
}

// round 8
// speedup vs baseline: 4.7858x; 1.1283x over previous
#include <cuda_runtime.h>
#include <cuda_fp16.h>
#include <cstdint>

#define CIN   64
#define COUT  64
#define HH    224
#define WW    224

// ---------------- smem layout (bytes) ----------------
// A: 514 position-rows x 128B (64 ci fp16), XOR swizzled. No W in smem.
#define A_OFF     0
#define A_ROWS    514
#define A_BYTES   (A_ROWS * 128)               // 65792
#define ALPHA_OFF (A_OFF + A_BYTES)
#define BIAS_OFF  (ALPHA_OFF + 256)
#define SMEM_TOTAL (BIAS_OFF + 256)            // 66304

// Plain ternary pattern [tap][co][ci] (fp16, exact)
__device__ __half g_plain[9 * COUT * CIN];
// Analytic mma B fragments: [tap][n8group(8)][kc(4)][lane(32)] x uint2
__device__ uint2 g_wfrag[9 * 8 * 4 * 32];
__device__ float g_alpha[COUT];

// ---------------------------------------------------------------------------
// Kernel 1: ternarize -> fp16 {-1,0,+1} pattern + per-cout alpha
// ---------------------------------------------------------------------------
__global__ void ternarize_kernel(const float* __restrict__ w) {
    __shared__ float red[256];
    __shared__ float red2[256];
    const int co  = blockIdx.x;
    const int tid = threadIdx.x;
    const float* wf = w + co * 576;

    float s = 0.f;
    for (int i = tid; i < 576; i += 256) s += fabsf(wf[i]);
    red[tid] = s;
    __syncthreads();
    for (int o = 128; o > 0; o >>= 1) {
        if (tid < o) red[tid] += red[tid + o];
        __syncthreads();
    }
    const float delta = (0.7f / 576.f) * red[0];
    __syncthreads();

    float cnt = 0.f, ms = 0.f;
    for (int i = tid; i < 576; i += 256) {
        float a = fabsf(wf[i]);
        if (a > delta) { cnt += 1.f; ms += a; }
    }
    red[tid] = ms; red2[tid] = cnt;
    __syncthreads();
    for (int o = 128; o > 0; o >>= 1) {
        if (tid < o) { red[tid] += red[tid + o]; red2[tid] += red2[tid + o]; }
        __syncthreads();
    }
    float count = (red2[0] == 0.f) ? 1.f : red2[0];
    float alpha = fmaxf(red[0] / count, 1e-4f);
    if (tid == 0) g_alpha[co] = alpha;

    // w index: [co][ci][tap]; emit g_plain[tap][co][ci]
    for (int i = tid; i < 576; i += 256) {
        int ci  = i / 9;
        int tap = i - ci * 9;
        float v = wf[i];
        float t = (v > delta) ? 1.f : ((v < -delta) ? -1.f : 0.f);
        g_plain[tap * 4096 + co * 64 + ci] = __float2half_rn(t);
    }
}

// ---------------------------------------------------------------------------
// Kernel 1b: pack B fragments in mma.m16n8k16 per-lane layout.
// lane holds B[k=2*(lane&3)+{0,1}][n=lane>>2] (word0) and k+8 (word1).
// ---------------------------------------------------------------------------
__global__ void pack_wfrag_kernel() {
    int tid = blockIdx.x * 256 + threadIdx.x;      // 0..9215
    if (tid >= 9 * 8 * 4 * 32) return;
    int lane = tid & 31;
    int kc   = (tid >> 5) & 3;
    int g    = (tid >> 7) & 7;
    int tap  = tid >> 10;

    int co = g * 8 + (lane >> 2);
    int k0 = kc * 16 + 2 * (lane & 3);
    const __half* p = g_plain + tap * 4096 + co * 64;

    __half2 w0 = __halves2half2(p[k0],     p[k0 + 1]);
    __half2 w1 = __halves2half2(p[k0 + 8], p[k0 + 9]);
    uint2 v;
    v.x = *(const uint32_t*)&w0;
    v.y = *(const uint32_t*)&w1;
    g_wfrag[((tap * 8 + g) * 4 + kc) * 32 + lane] = v;
}

// ---------------------------------------------------------------------------
// Baseline-PTX helpers
// ---------------------------------------------------------------------------
__device__ __forceinline__ uint32_t smem_u32(const void* p) {
    uint32_t a;
    asm("{ .reg .u64 t; cvta.to.shared.u64 t, %1; cvt.u32.u64 %0, t; }" : "=r"(a) : "l"(p));
    return a;
}
__device__ __forceinline__ void ldsm_x4(uint32_t* r, uint32_t addr) {
    asm volatile("ldmatrix.sync.aligned.m8n8.x4.shared.b16 {%0,%1,%2,%3}, [%4];"
                 : "=r"(r[0]), "=r"(r[1]), "=r"(r[2]), "=r"(r[3]) : "r"(addr));
}
__device__ __forceinline__ void mma16816(float* d, const uint32_t* a, const uint32_t* b) {
    asm volatile("mma.sync.aligned.m16n8k16.row.col.f32.f16.f16.f32 "
                 "{%0,%1,%2,%3}, {%4,%5,%6,%7}, {%8,%9}, {%0,%1,%2,%3};"
                 : "+f"(d[0]), "+f"(d[1]), "+f"(d[2]), "+f"(d[3])
                 : "r"(a[0]), "r"(a[1]), "r"(a[2]), "r"(a[3]), "r"(b[0]), "r"(b[1]));
}

// ---------------------------------------------------------------------------
// Kernel 2: fp16 mma.sync implicit conv, 256 threads, 2 CTAs/SM.
// CTA strip: 8 input rows x 64 cols (6x62 valid), positions 0..511 in smem
// rows 1..512 (+ zero guard rows 0, 513). 3 M=128 tiles x N=64.
// 8 warps: warp tile m32 (wid&3) x n32 (wid>>2); tile-outer, B frags
// loaded from g_wfrag via coalesced LDG.64 (L1-hot), A via ldmatrix.
// ---------------------------------------------------------------------------
__global__ __launch_bounds__(256, 2)
void conv_mma_kernel(const float* __restrict__ x,
                     const float* __restrict__ bias,
                     float* __restrict__ out) {
    extern __shared__ char smem[];
    const uint32_t sb  = smem_u32(smem);
    const int tid  = threadIdx.x;
    const int wid  = tid >> 5;
    const int lane = tid & 31;

    const int w0 = blockIdx.x * 62;
    const int h0 = blockIdx.y * 6;
    const int n  = blockIdx.z;

    if (tid < 64) {
        *(float*)(smem + ALPHA_OFF + tid * 4) = g_alpha[tid];
        *(float*)(smem + BIAS_OFF  + tid * 4) = __ldg(&bias[tid]);
    }
    // zero guard rows 0 and 513 (128B each)
    if (tid >= 64 && tid < 128) {
        int j = tid - 64;
        int off = (j < 32) ? j * 4 : (513 * 128 + (j - 32) * 4);
        *(float*)(smem + A_OFF + off) = 0.f;
    }

    // ---- stage A: strip -> fp16, one 16B unit (8 ci) per task
    {
        const float* xn = x + (size_t)n * CIN * HH * WW;
        for (int i = tid; i < 4096; i += 256) {       // 512 pos x 8 octets
            int p = i & 511;
            int o = i >> 9;
            int r = p >> 6, c = p & 63;
            int h = h0 + r - 1, w = w0 + c - 1;
            bool inb = ((unsigned)h < HH) && ((unsigned)w < WW);
            uint32_t hw[4];
            #pragma unroll
            for (int j = 0; j < 4; j++) {
                float v0 = 0.f, v1 = 0.f;
                if (inb) {
                    const float* bp = xn + ((size_t)(o * 8 + 2 * j) * HH + h) * WW + w;
                    v0 = __ldg(bp);
                    v1 = __ldg(bp + (size_t)HH * WW);
                }
                __half2 hv = __floats2half2_rn(v0, v1);
                hw[j] = *(const uint32_t*)&hv;
            }
            int row = p + 1;
            uint32_t off = (uint32_t)(A_OFF + row * 128) + (uint32_t)((o ^ (row & 7)) << 4);
            *(uint4*)(smem + off) = make_uint4(hw[0], hw[1], hw[2], hw[3]);
        }
    }
    __syncthreads();

    // ---- compute
    const int wm  = wid & 3;         // 0..3 (M slice, m32)
    const int wn  = wid >> 2;        // 0..1 (N slice, n32)
    const int n0g = wn * 4;          // first n8-group

    const int a_row = lane & 15;
    const int a_uo  = lane >> 4;     // 0..1

    const float* al = (const float*)(smem + ALPHA_OFF);
    const float* bi = (const float*)(smem + BIAS_OFF);

    #pragma unroll 1
    for (int t = 0; t < 3; t++) {
        float acc[2][4][4];
        #pragma unroll
        for (int mc = 0; mc < 2; mc++)
            #pragma unroll
            for (int nc = 0; nc < 4; nc++)
                #pragma unroll
                for (int q = 0; q < 4; q++) acc[mc][nc][q] = 0.f;

        const int pt = 64 + t * 128 + wm * 32;

        #pragma unroll 1
        for (int tap = 0; tap < 9; tap++) {
            const int shift = (tap / 3) * 64 + (tap % 3) - 65;
            const uint2* wf = g_wfrag + (size_t)(tap * 8 + n0g) * 128 + lane;

            #pragma unroll
            for (int kc = 0; kc < 4; kc++) {
                uint2 bfr[4];
                #pragma unroll
                for (int nc = 0; nc < 4; nc++)
                    bfr[nc] = __ldg(wf + (nc * 4 + kc) * 32);

                #pragma unroll
                for (int mc = 0; mc < 2; mc++) {
                    int row = pt + mc * 16 + 1 + shift + a_row;
                    int u   = kc * 2 + a_uo;
                    uint32_t addr = sb + A_OFF + (uint32_t)(row * 128)
                                  + (uint32_t)((u ^ (row & 7)) << 4);
                    uint32_t afr[4];
                    ldsm_x4(afr, addr);
                    #pragma unroll
                    for (int nc = 0; nc < 4; nc++)
                        mma16816(acc[mc][nc], afr, (const uint32_t*)&bfr[nc]);
                }
            }
        }

        // ---- epilogue tile t: alpha*d + bias
        #pragma unroll
        for (int mc = 0; mc < 2; mc++) {
            #pragma unroll
            for (int rr = 0; rr < 2; rr++) {
                const int p = pt + mc * 16 + rr * 8 + (lane >> 2);
                const int c = p & 63, r = p >> 6;
                const int h = h0 + r - 1, w = w0 + c - 1;
                if (c >= 1 && c <= 62 && h < HH && w < WW) {
                    float* ob = out + (((size_t)n * COUT) * HH + h) * WW + w;
                    #pragma unroll
                    for (int nc = 0; nc < 4; nc++) {
                        const int co = wn * 32 + nc * 8 + 2 * (lane & 3);
                        float v0 = acc[mc][nc][rr * 2 + 0] * al[co]     + bi[co];
                        float v1 = acc[mc][nc][rr * 2 + 1] * al[co + 1] + bi[co + 1];
                        ob[(size_t)co       * HH * WW] = v0;
                        ob[(size_t)(co + 1) * HH * WW] = v1;
                    }
                }
            }
        }
    }
}

// ---------------------------------------------------------------------------
extern "C" void kernel_launch(void* const* d_in, const int* in_sizes, int n_in,
                              void* d_out, int out_size) {
    const float* x      = (const float*)d_in[0];
    const float* weight = (const float*)d_in[1];
    const float* bias   = (const float*)d_in[2];
    float* out          = (float*)d_out;

    cudaFuncSetAttribute(conv_mma_kernel,
                         cudaFuncAttributeMaxDynamicSharedMemorySize, SMEM_TOTAL);

    ternarize_kernel<<<COUT, 256>>>(weight);
    pack_wfrag_kernel<<<36, 256>>>();
    dim3 grid(4, 38, 16);   // 4 W-strips (62 wide), 38 H-strips (6 tall), N=16
    conv_mma_kernel<<<grid, 256, SMEM_TOTAL>>>(x, bias, out);
}